// round 12
// baseline (speedup 1.0000x reference)
#include <cuda_runtime.h>
#include <math.h>

#define BATCH 32
#define SEQ 4096
#define HIDDEN 2048
#define ROUTE_H 256
#define NUM_EXPERTS 64
#define TOP_K 8
#define LN_EPS 1e-5f

#define PSPLIT 64                    // pool items per batch (64 rows each)
#define PROWS (SEQ / PSPLIT)         // 64 seq rows per pool item
#define POOL_ITEMS (BATCH * PSPLIT)  // 2048
#define H4 (HIDDEN / 4)              // 512 float4 columns

#define GSPLIT 16                    // GEMV1 K-slices per batch
#define KCHUNK (HIDDEN / GSPLIT)     // 128 hidden cols per slice
#define NTHR 512
#define NBLK (BATCH * GSPLIT)        // 512 blocks (one co-resident wave)

// Scratch (no cudaMalloc allowed). Zero-init at load; counters reset at the
// end of every launch (after all uses complete) -> graph-replay safe.
__device__ float g_partial[POOL_ITEMS * HIDDEN];      // [item][h] = 16 MB
__device__ float g_hpart[GSPLIT * BATCH * ROUTE_H];   // [gs][b][j] = 512 KB
__device__ unsigned int g_qhead;                      // pool work queue head
__device__ unsigned int g_done[BATCH];                // pool items done / batch
__device__ unsigned int g_cnt2[BATCH];                // gemv done / batch
__device__ unsigned int g_fin;                        // finales done

// ---------------------------------------------------------------------------
// ONE fused kernel, 512 blocks x 512 threads = one co-resident wave.
// Pool loop pulls 64-row items (batch-major) off a global queue; after each
// item the block checks whether its own GEMV batch is fully pooled and, if
// so, runs its GEMV1 slice (+ possibly the batch finale) INSIDE the loop,
// overlapped with other blocks' streaming. Batches complete pooling in a
// staggered order, so only the last batch's router work is exposed at the end.
// All reduction orders fixed -> deterministic regardless of scheduling.
// ---------------------------------------------------------------------------
__global__ void __launch_bounds__(NTHR) fused_router(
    const float* __restrict__ x,
    const float* __restrict__ W1, const float* __restrict__ b1,
    const float* __restrict__ ln_g, const float* __restrict__ ln_b,
    const float* __restrict__ W2, const float* __restrict__ b2,
    float* __restrict__ out)
{
    __shared__ unsigned int s_item;
    __shared__ unsigned int s_go;
    __shared__ unsigned int s_flag;
    __shared__ float sh_fold[4][KCHUNK];
    __shared__ float sh_pool[KCHUNK];
    __shared__ float sh_gacc[2][ROUTE_H];
    __shared__ float sh_h[ROUTE_H];
    __shared__ float sh_w1r[8], sh_w2r[8];
    __shared__ float sh_part[ROUTE_H];
    __shared__ float sh_logits[NUM_EXPERTS];

    int blk = blockIdx.x;
    int t   = threadIdx.x;           // 0..511
    int gb  = blk >> 4;              // this block's GEMV batch 0..31
    int gs  = blk & (GSPLIT - 1);    // this block's GEMV K-slice 0..15

    bool gemv_done = false;

    // ================= pool loop with interleaved router work ==============
    for (;;) {
        if (t == 0) s_item = atomicAdd(&g_qhead, 1u);
        __syncthreads();
        unsigned int item = s_item;
        if (item >= POOL_ITEMS) break;

        int pb = item >> 6;          // batch (batch-major order)
        int ps = item & (PSPLIT - 1);

        const float4* base = (const float4*)(x) +
            ((size_t)pb * SEQ + (size_t)ps * PROWS) * (size_t)H4 + t;
        float4 acc = make_float4(0.f, 0.f, 0.f, 0.f);
#pragma unroll 8
        for (int s = 0; s < PROWS; s++) {
            float4 v = __ldcs(&base[(size_t)s * H4]);
            acc.x += v.x; acc.y += v.y; acc.z += v.z; acc.w += v.w;
        }
        ((float4*)(g_partial + (size_t)item * HIDDEN))[t] = acc;

        __threadfence();             // publish this item's partial
        __syncthreads();
        if (t == 0) atomicAdd(&g_done[pb], 1u);

        // ---- opportunistic GEMV: my batch fully pooled? ----
        if (!gemv_done) {
            if (t == 0)
                s_go = (((volatile unsigned int*)g_done)[gb] >= PSPLIT) ? 1u : 0u;
            __syncthreads();
            if (s_go) { gemv_done = true; goto do_gemv; }
        }
        continue;

    do_gemv:
        __threadfence();             // acquire all PSPLIT partial slices
        {
            int i0 = gs * KCHUNK;

            // Fold 64 partials for 128 cols: (col = t&127, part = t>>7),
            // each folds 16 partials in 2 independent chains.
            {
                int col  = t & (KCHUNK - 1);
                int part = t >> 7;   // 0..3
                const float* p = g_partial +
                    ((size_t)gb * PSPLIT + part * 16) * HIDDEN + i0 + col;
                float sA = 0.f, sB = 0.f;
#pragma unroll
                for (int q = 0; q < 8; q++) {
                    sA += p[(size_t)(2 * q)     * HIDDEN];
                    sB += p[(size_t)(2 * q + 1) * HIDDEN];
                }
                sh_fold[part][col] = sA + sB;
            }
            __syncthreads();
            if (t < KCHUNK) {
                sh_pool[t] = ((sh_fold[0][t] + sh_fold[1][t]) +
                              (sh_fold[2][t] + sh_fold[3][t])) * (1.0f / SEQ);
            }
            __syncthreads();

            // GEMV slice: 512 threads = 256 outputs x 2 row-halves of 64.
            {
                int j    = t & (ROUTE_H - 1);
                int half = t >> 8;   // 0 or 1
                int r0   = i0 + half * 64;
                float a0 = 0.f, a1 = 0.f, a2 = 0.f, a3 = 0.f;
                float a4 = 0.f, a5 = 0.f, a6 = 0.f, a7 = 0.f;
#pragma unroll
                for (int r = 0; r < 64; r += 8) {
                    const float* w = W1 + (size_t)(r0 + r) * ROUTE_H + j;
                    int p = half * 64 + r;
                    a0 += sh_pool[p + 0] * w[0 * ROUTE_H];
                    a1 += sh_pool[p + 1] * w[1 * ROUTE_H];
                    a2 += sh_pool[p + 2] * w[2 * ROUTE_H];
                    a3 += sh_pool[p + 3] * w[3 * ROUTE_H];
                    a4 += sh_pool[p + 4] * w[4 * ROUTE_H];
                    a5 += sh_pool[p + 5] * w[5 * ROUTE_H];
                    a6 += sh_pool[p + 6] * w[6 * ROUTE_H];
                    a7 += sh_pool[p + 7] * w[7 * ROUTE_H];
                }
                sh_gacc[half][j] =
                    ((a0 + a1) + (a2 + a3)) + ((a4 + a5) + (a6 + a7));
            }
            __syncthreads();
            if (t < ROUTE_H)
                g_hpart[((size_t)gs * BATCH + gb) * ROUTE_H + t] =
                    sh_gacc[0][t] + sh_gacc[1][t];

            // election: last GEMV block of batch gb runs the finale
            __threadfence();         // publish h-partial slice
            __syncthreads();
            if (t == 0) {
                unsigned int old = atomicAdd(&g_cnt2[gb], 1u);
                s_flag = (old == GSPLIT - 1) ? 1u : 0u;
            }
            __syncthreads();
            if (s_flag) {
                __threadfence();     // acquire all 16 h-slices

                // ---------------- finale (first 256 threads) ----------------
                if (t < ROUTE_H) {
                    int j    = t;
                    int lane = t & 31;
                    int warp = t >> 5;

                    float h = 0.f;
#pragma unroll
                    for (int k = 0; k < GSPLIT; k++)
                        h += g_hpart[((size_t)k * BATCH + gb) * ROUTE_H + j];
                    h += b1[j];

                    float s1 = h, s2 = h * h;
#pragma unroll
                    for (int o = 16; o > 0; o >>= 1) {
                        s1 += __shfl_xor_sync(0xffffffffu, s1, o);
                        s2 += __shfl_xor_sync(0xffffffffu, s2, o);
                    }
                    if (lane == 0) { sh_w1r[warp] = s1; sh_w2r[warp] = s2; }
                    __syncwarp();
                    asm volatile("bar.sync 1, 256;" ::: "memory");
                    float t1 = sh_w1r[lane & 7], t2 = sh_w2r[lane & 7];
#pragma unroll
                    for (int o = 4; o > 0; o >>= 1) {
                        t1 += __shfl_xor_sync(0xffffffffu, t1, o);
                        t2 += __shfl_xor_sync(0xffffffffu, t2, o);
                    }
                    t1 = __shfl_sync(0xffffffffu, t1, 0);
                    t2 = __shfl_sync(0xffffffffu, t2, 0);

                    float mu  = t1 * (1.0f / ROUTE_H);
                    float ms  = t2 * (1.0f / ROUTE_H);
                    float inv = rsqrtf(ms - mu * mu + LN_EPS);
                    h = (h - mu) * inv * ln_g[j] + ln_b[j];
                    h = 0.5f * h * (1.0f + erff(h * 0.70710678118654752f));
                    sh_h[j] = h;
                    asm volatile("bar.sync 1, 256;" ::: "memory");

                    {   // GEMV2, K-split 4: 256 threads = 64 experts x 4
                        int e   = j & (NUM_EXPERTS - 1);
                        int ks2 = j >> 6;
                        int r0  = ks2 * (ROUTE_H / 4);
                        float a = 0.f;
#pragma unroll 8
                        for (int i = 0; i < ROUTE_H / 4; i++)
                            a += sh_h[r0 + i] * W2[(size_t)(r0 + i) * NUM_EXPERTS + e];
                        sh_part[j] = a;
                    }
                    asm volatile("bar.sync 1, 256;" ::: "memory");
                    if (j < NUM_EXPERTS) {
                        sh_logits[j] = ((sh_part[j] + sh_part[j + 64]) +
                                        (sh_part[j + 128] + sh_part[j + 192]))
                                       + b2[j];
                        out[(size_t)gb * NUM_EXPERTS + j] = 0.0f;
                    }
                    asm volatile("bar.sync 1, 256;" ::: "memory");

                    // top-8 + softmax + scatter; strict '>' = first-index
                    // tie-break (jax.lax.top_k). Then counter resets.
                    if (j == 0) {
                        int   idx[TOP_K];
                        float val[TOP_K];
                        unsigned long long used = 0ull;
                        for (int k = 0; k < TOP_K; k++) {
                            float best = -INFINITY;
                            int bi = 0;
                            for (int e = 0; e < NUM_EXPERTS; e++) {
                                if (!((used >> e) & 1ull) && sh_logits[e] > best) {
                                    best = sh_logits[e]; bi = e;
                                }
                            }
                            used |= (1ull << bi);
                            idx[k] = bi;
                            val[k] = best;
                        }
                        float mx = val[0];
                        float denom = 0.f;
                        float ex[TOP_K];
                        for (int k = 0; k < TOP_K; k++) {
                            ex[k] = expf(val[k] - mx); denom += ex[k];
                        }
                        float rden = 1.0f / denom;
                        for (int k = 0; k < TOP_K; k++)
                            out[(size_t)gb * NUM_EXPERTS + idx[k]] = ex[k] * rden;

                        // all 16 GEMV blocks of gb have passed their g_done
                        // check (g_cnt2 hit 16), so these resets are safe.
                        g_done[gb] = 0u;
                        g_cnt2[gb] = 0u;
                        __threadfence();
                        unsigned int f = atomicAdd(&g_fin, 1u);
                        if (f == BATCH - 1) { g_qhead = 0u; g_fin = 0u; }
                    }
                }
                __syncthreads();
            }
        }
    }

    // ============ fallback: stream done but my GEMV not yet run ============
    if (!gemv_done) {
        if (t == 0) {
            while (((volatile unsigned int*)g_done)[gb] < PSPLIT) { }
            s_go = 1u;
        }
        __syncthreads();
        gemv_done = true;
        // jump back into the GEMV path exactly once
        goto do_gemv_tail;
    }
    return;

do_gemv_tail:
    // Re-enter the pool loop body's GEMV by replicating the jump:
    // (the loop's `do_gemv` label is inside the for; duplicate via a call to
    //  the same code path — achieved by restarting the loop with an empty
    //  queue: s_item >= POOL_ITEMS immediately breaks after GEMV.)
    {
        // Direct inline: identical to do_gemv block above.
        __threadfence();
        int i0 = gs * KCHUNK;
        {
            int col  = t & (KCHUNK - 1);
            int part = t >> 7;
            const float* p = g_partial +
                ((size_t)gb * PSPLIT + part * 16) * HIDDEN + i0 + col;
            float sA = 0.f, sB = 0.f;
#pragma unroll
            for (int q = 0; q < 8; q++) {
                sA += p[(size_t)(2 * q)     * HIDDEN];
                sB += p[(size_t)(2 * q + 1) * HIDDEN];
            }
            sh_fold[part][col] = sA + sB;
        }
        __syncthreads();
        if (t < KCHUNK) {
            sh_pool[t] = ((sh_fold[0][t] + sh_fold[1][t]) +
                          (sh_fold[2][t] + sh_fold[3][t])) * (1.0f / SEQ);
        }
        __syncthreads();
        {
            int j    = t & (ROUTE_H - 1);
            int half = t >> 8;
            int r0   = i0 + half * 64;
            float a0 = 0.f, a1 = 0.f, a2 = 0.f, a3 = 0.f;
            float a4 = 0.f, a5 = 0.f, a6 = 0.f, a7 = 0.f;
#pragma unroll
            for (int r = 0; r < 64; r += 8) {
                const float* w = W1 + (size_t)(r0 + r) * ROUTE_H + j;
                int p = half * 64 + r;
                a0 += sh_pool[p + 0] * w[0 * ROUTE_H];
                a1 += sh_pool[p + 1] * w[1 * ROUTE_H];
                a2 += sh_pool[p + 2] * w[2 * ROUTE_H];
                a3 += sh_pool[p + 3] * w[3 * ROUTE_H];
                a4 += sh_pool[p + 4] * w[4 * ROUTE_H];
                a5 += sh_pool[p + 5] * w[5 * ROUTE_H];
                a6 += sh_pool[p + 6] * w[6 * ROUTE_H];
                a7 += sh_pool[p + 7] * w[7 * ROUTE_H];
            }
            sh_gacc[half][j] = ((a0 + a1) + (a2 + a3)) + ((a4 + a5) + (a6 + a7));
        }
        __syncthreads();
        if (t < ROUTE_H)
            g_hpart[((size_t)gs * BATCH + gb) * ROUTE_H + t] =
                sh_gacc[0][t] + sh_gacc[1][t];

        __threadfence();
        __syncthreads();
        if (t == 0) {
            unsigned int old = atomicAdd(&g_cnt2[gb], 1u);
            s_flag = (old == GSPLIT - 1) ? 1u : 0u;
        }
        __syncthreads();
        if (!s_flag) return;
        __threadfence();

        if (t < ROUTE_H) {
            int j    = t;
            int lane = t & 31;
            int warp = t >> 5;

            float h = 0.f;
#pragma unroll
            for (int k = 0; k < GSPLIT; k++)
                h += g_hpart[((size_t)k * BATCH + gb) * ROUTE_H + j];
            h += b1[j];

            float s1 = h, s2 = h * h;
#pragma unroll
            for (int o = 16; o > 0; o >>= 1) {
                s1 += __shfl_xor_sync(0xffffffffu, s1, o);
                s2 += __shfl_xor_sync(0xffffffffu, s2, o);
            }
            if (lane == 0) { sh_w1r[warp] = s1; sh_w2r[warp] = s2; }
            __syncwarp();
            asm volatile("bar.sync 1, 256;" ::: "memory");
            float t1 = sh_w1r[lane & 7], t2 = sh_w2r[lane & 7];
#pragma unroll
            for (int o = 4; o > 0; o >>= 1) {
                t1 += __shfl_xor_sync(0xffffffffu, t1, o);
                t2 += __shfl_xor_sync(0xffffffffu, t2, o);
            }
            t1 = __shfl_sync(0xffffffffu, t1, 0);
            t2 = __shfl_sync(0xffffffffu, t2, 0);

            float mu  = t1 * (1.0f / ROUTE_H);
            float ms  = t2 * (1.0f / ROUTE_H);
            float inv = rsqrtf(ms - mu * mu + LN_EPS);
            h = (h - mu) * inv * ln_g[j] + ln_b[j];
            h = 0.5f * h * (1.0f + erff(h * 0.70710678118654752f));
            sh_h[j] = h;
            asm volatile("bar.sync 1, 256;" ::: "memory");

            {
                int e   = j & (NUM_EXPERTS - 1);
                int ks2 = j >> 6;
                int r0  = ks2 * (ROUTE_H / 4);
                float a = 0.f;
#pragma unroll 8
                for (int i = 0; i < ROUTE_H / 4; i++)
                    a += sh_h[r0 + i] * W2[(size_t)(r0 + i) * NUM_EXPERTS + e];
                sh_part[j] = a;
            }
            asm volatile("bar.sync 1, 256;" ::: "memory");
            if (j < NUM_EXPERTS) {
                sh_logits[j] = ((sh_part[j] + sh_part[j + 64]) +
                                (sh_part[j + 128] + sh_part[j + 192])) + b2[j];
                out[(size_t)gb * NUM_EXPERTS + j] = 0.0f;
            }
            asm volatile("bar.sync 1, 256;" ::: "memory");

            if (j == 0) {
                int   idx[TOP_K];
                float val[TOP_K];
                unsigned long long used = 0ull;
                for (int k = 0; k < TOP_K; k++) {
                    float best = -INFINITY;
                    int bi = 0;
                    for (int e = 0; e < NUM_EXPERTS; e++) {
                        if (!((used >> e) & 1ull) && sh_logits[e] > best) {
                            best = sh_logits[e]; bi = e;
                        }
                    }
                    used |= (1ull << bi);
                    idx[k] = bi;
                    val[k] = best;
                }
                float mx = val[0];
                float denom = 0.f;
                float ex[TOP_K];
                for (int k = 0; k < TOP_K; k++) {
                    ex[k] = expf(val[k] - mx); denom += ex[k];
                }
                float rden = 1.0f / denom;
                for (int k = 0; k < TOP_K; k++)
                    out[(size_t)gb * NUM_EXPERTS + idx[k]] = ex[k] * rden;

                g_done[gb] = 0u;
                g_cnt2[gb] = 0u;
                __threadfence();
                unsigned int f = atomicAdd(&g_fin, 1u);
                if (f == BATCH - 1) { g_qhead = 0u; g_fin = 0u; }
            }
        }
    }
}

// ---------------------------------------------------------------------------
extern "C" void kernel_launch(void* const* d_in, const int* in_sizes, int n_in,
                              void* d_out, int out_size) {
    const float* hs   = (const float*)d_in[0];
    const float* W1   = (const float*)d_in[1];
    const float* b1   = (const float*)d_in[2];
    const float* ln_g = (const float*)d_in[3];
    const float* ln_b = (const float*)d_in[4];
    const float* W2   = (const float*)d_in[5];
    const float* b2   = (const float*)d_in[6];
    // d_in[7] = top_k (hardcoded 8)

    float* out = (float*)d_out;

    fused_router<<<NBLK, NTHR>>>(hs, W1, b1, ln_g, ln_b, W2, b2, out);
}

// round 13
// speedup vs baseline: 1.1123x; 1.1123x over previous
#include <cuda_runtime.h>
#include <math.h>

#define BATCH 32
#define SEQ 4096
#define HIDDEN 2048
#define ROUTE_H 256
#define NUM_EXPERTS 64
#define TOP_K 8
#define LN_EPS 1e-5f

#define NSPLIT 16                    // blocks per batch (also K-split for GEMV1)
#define SCHUNK (SEQ / NSPLIT)        // 256 seq rows per block
#define H4 (HIDDEN / 4)              // 512 float4 columns
#define KCHUNK (HIDDEN / NSPLIT)     // 128 hidden cols per GEMV1 slice
#define NTHR 512
#define PF_AT 192                    // pool iteration at which to prefetch W1

// Scratch (no cudaMalloc allowed). Zero-initialized at module load; counters
// are reset by the finale block each launch -> graph-replay safe.
__device__ float g_partial[NSPLIT * BATCH * HIDDEN];   // [sp][b][h] = 4 MB
__device__ float g_hpart[NSPLIT * BATCH * ROUTE_H];    // [ks][b][j] = 512 KB
__device__ unsigned int g_cnt1[BATCH];                 // pool-done election
__device__ unsigned int g_cnt2[BATCH];                 // gemv-done election

// ---------------------------------------------------------------------------
// ONE fused kernel. grid = BATCH*NSPLIT = 512 blocks x 512 threads = exactly
// one resident wave (<= 148 SMs x 4 CTAs) -> all blocks co-resident, so the
// per-batch spin-wait cannot deadlock.
// Phase 1: pool partial for (b, sp) with __ldcs streaming loads. At 75% of
//   the loop, prefetch this block's W1 slice (and W2) into L2 so the GEMV's
//   weight fetch overlaps the last ~2.5us of streaming instead of stalling
//   cold at DRAM after it.
// Phase 2: spin until batch b fully pooled, fold, GEMV1 K-slice.
// Phase 3: last finishing block of batch b runs LN + GELU + GEMV2 + top-8.
// All reduction orders are fixed -> deterministic output.
// ---------------------------------------------------------------------------
__global__ void __launch_bounds__(NTHR) fused_router(
    const float* __restrict__ x,
    const float* __restrict__ W1, const float* __restrict__ b1,
    const float* __restrict__ ln_g, const float* __restrict__ ln_b,
    const float* __restrict__ W2, const float* __restrict__ b2,
    float* __restrict__ out)
{
    __shared__ float sh_fold[4][KCHUNK];
    __shared__ float sh_pool[KCHUNK];
    __shared__ float sh_gacc[2][ROUTE_H];
    __shared__ unsigned int s_flag;

    int blk = blockIdx.x;
    int b   = blk / NSPLIT;
    int sp  = blk % NSPLIT;
    int t   = threadIdx.x;           // 0..511

    // ---------------- Phase 1: partial mean-pool ----------------
    {
        const float4* base = (const float4*)(x) +
            ((size_t)b * SEQ + (size_t)sp * SCHUNK) * (size_t)H4 + t;
        float4 acc = make_float4(0.f, 0.f, 0.f, 0.f);

        // First 192 iterations of streaming.
#pragma unroll 8
        for (int s = 0; s < PF_AT; s++) {
            float4 v = __ldcs(&base[(size_t)s * H4]);
            acc.x += v.x; acc.y += v.y; acc.z += v.z; acc.w += v.w;
        }

        // Late L2 prefetch: this block's W1 GEMV slice (128 KB = 1024 lines,
        // 2 per thread). ~2.5us before use; evict-first stream lines won't
        // displace these. gs==sp here (same block does slice sp).
        {
            const float* sbase = W1 + (size_t)sp * KCHUNK * ROUTE_H;
            asm volatile("prefetch.global.L2 [%0];" :: "l"(sbase + (size_t)t * 32));
            asm volatile("prefetch.global.L2 [%0];"
                         :: "l"(sbase + (size_t)(t + NTHR) * 32));
            if (sp == 0) {   // one block per batch warms W2 (64 KB = 512 lines)
                asm volatile("prefetch.global.L2 [%0];" :: "l"(W2 + (size_t)t * 32));
            }
        }

        // Remaining 64 iterations.
#pragma unroll 8
        for (int s = PF_AT; s < SCHUNK; s++) {
            float4 v = __ldcs(&base[(size_t)s * H4]);
            acc.x += v.x; acc.y += v.y; acc.z += v.z; acc.w += v.w;
        }

        float4* o = (float4*)(g_partial + ((size_t)sp * BATCH + b) * HIDDEN);
        o[t] = acc;
    }

    // ---------------- arrive + spin until batch b pooled ----------------
    __threadfence();                       // publish partials
    __syncthreads();
    if (t == 0) {
        atomicAdd(&g_cnt1[b], 1u);
        while (((volatile unsigned int*)g_cnt1)[b] < NSPLIT) { }
    }
    __syncthreads();
    __threadfence();                       // acquire all 16 partial slices

    // ---------------- Phase 2: GEMV1 K-slice for cols [sp*128, +128) -------
    int i0 = sp * KCHUNK;

    // Fold 16 partials for 128 columns: thread (col = t&127, part = t>>7)
    // folds 4 partials; combine below. (L2-resident: just written.)
    {
        int col  = t & (KCHUNK - 1);
        int part = t >> 7;                 // 0..3
        float s = 0.f;
#pragma unroll
        for (int q = 0; q < NSPLIT / 4; q++) {
            int spp = part * (NSPLIT / 4) + q;
            s += g_partial[((size_t)spp * BATCH + b) * HIDDEN + i0 + col];
        }
        sh_fold[part][col] = s;
    }
    __syncthreads();
    if (t < KCHUNK) {
        sh_pool[t] = ((sh_fold[0][t] + sh_fold[1][t]) +
                      (sh_fold[2][t] + sh_fold[3][t])) * (1.0f / SEQ);
    }
    __syncthreads();

    // GEMV slice: 512 threads = 256 outputs x 2 row-halves of 64 rows.
    // 8 independent accumulators; W1 reads coalesced across j (L2-warm).
    {
        int j    = t & (ROUTE_H - 1);
        int half = t >> 8;                 // 0 or 1
        int r0   = i0 + half * 64;
        float a0 = 0.f, a1 = 0.f, a2 = 0.f, a3 = 0.f;
        float a4 = 0.f, a5 = 0.f, a6 = 0.f, a7 = 0.f;
#pragma unroll
        for (int r = 0; r < 64; r += 8) {
            const float* w = W1 + (size_t)(r0 + r) * ROUTE_H + j;
            int p = half * 64 + r;
            a0 += sh_pool[p + 0] * w[0 * ROUTE_H];
            a1 += sh_pool[p + 1] * w[1 * ROUTE_H];
            a2 += sh_pool[p + 2] * w[2 * ROUTE_H];
            a3 += sh_pool[p + 3] * w[3 * ROUTE_H];
            a4 += sh_pool[p + 4] * w[4 * ROUTE_H];
            a5 += sh_pool[p + 5] * w[5 * ROUTE_H];
            a6 += sh_pool[p + 6] * w[6 * ROUTE_H];
            a7 += sh_pool[p + 7] * w[7 * ROUTE_H];
        }
        sh_gacc[half][j] = ((a0 + a1) + (a2 + a3)) + ((a4 + a5) + (a6 + a7));
    }
    __syncthreads();
    if (t < ROUTE_H)
        g_hpart[((size_t)sp * BATCH + b) * ROUTE_H + t] =
            sh_gacc[0][t] + sh_gacc[1][t];

    // ---------------- election: last GEMV block runs the finale ------------
    __threadfence();                       // publish h-partial slice
    __syncthreads();
    if (t == 0) {
        unsigned int old = atomicAdd(&g_cnt2[b], 1u);
        s_flag = (old == NSPLIT - 1) ? 1u : 0u;
    }
    __syncthreads();
    if (!s_flag) return;
    __threadfence();                       // acquire all 16 h-slices

    // ---------------- Phase 3: finale (first 256 threads) ------------------
    __shared__ float sh_h[ROUTE_H];
    __shared__ float sh_w1r[8], sh_w2r[8];
    __shared__ float sh_part[ROUTE_H];
    __shared__ float sh_logits[NUM_EXPERTS];

    if (t < ROUTE_H) {
        int j    = t;
        int lane = t & 31;
        int warp = t >> 5;

        float h = 0.f;
#pragma unroll
        for (int k = 0; k < NSPLIT; k++)
            h += g_hpart[((size_t)k * BATCH + b) * ROUTE_H + j];
        h += b1[j];

        // LN reduce via warp shuffles (8 warps)
        float s1 = h, s2 = h * h;
#pragma unroll
        for (int o = 16; o > 0; o >>= 1) {
            s1 += __shfl_xor_sync(0xffffffffu, s1, o);
            s2 += __shfl_xor_sync(0xffffffffu, s2, o);
        }
        if (lane == 0) { sh_w1r[warp] = s1; sh_w2r[warp] = s2; }
        __syncwarp();
        asm volatile("bar.sync 1, 256;" ::: "memory");
        float t1 = sh_w1r[lane & 7], t2 = sh_w2r[lane & 7];
#pragma unroll
        for (int o = 4; o > 0; o >>= 1) {
            t1 += __shfl_xor_sync(0xffffffffu, t1, o);
            t2 += __shfl_xor_sync(0xffffffffu, t2, o);
        }
        t1 = __shfl_sync(0xffffffffu, t1, 0);
        t2 = __shfl_sync(0xffffffffu, t2, 0);

        float mu  = t1 * (1.0f / ROUTE_H);
        float ms  = t2 * (1.0f / ROUTE_H);
        float inv = rsqrtf(ms - mu * mu + LN_EPS);
        h = (h - mu) * inv * ln_g[j] + ln_b[j];
        h = 0.5f * h * (1.0f + erff(h * 0.70710678118654752f)); // exact GELU
        sh_h[j] = h;
        asm volatile("bar.sync 1, 256;" ::: "memory");

        // GEMV2, K-split 4: 256 threads = 64 experts x 4 slices
        {
            int e   = j & (NUM_EXPERTS - 1);
            int ks2 = j >> 6;
            int r0  = ks2 * (ROUTE_H / 4);
            float a = 0.f;
#pragma unroll 8
            for (int i = 0; i < ROUTE_H / 4; i++)
                a += sh_h[r0 + i] * W2[(size_t)(r0 + i) * NUM_EXPERTS + e];
            sh_part[j] = a;
        }
        asm volatile("bar.sync 1, 256;" ::: "memory");
        if (j < NUM_EXPERTS) {
            sh_logits[j] = ((sh_part[j] + sh_part[j + 64]) +
                            (sh_part[j + 128] + sh_part[j + 192])) + b2[j];
            out[(size_t)b * NUM_EXPERTS + j] = 0.0f;  // d_out poisoned
        }
        asm volatile("bar.sync 1, 256;" ::: "memory");

        // top-8 + softmax + scatter (strict '>' = first-index tie-break,
        // matching jax.lax.top_k). Also reset counters for next graph replay.
        if (j == 0) {
            int   idx[TOP_K];
            float val[TOP_K];
            unsigned long long used = 0ull;
            for (int k = 0; k < TOP_K; k++) {
                float best = -INFINITY;
                int bi = 0;
                for (int e = 0; e < NUM_EXPERTS; e++) {
                    if (!((used >> e) & 1ull) && sh_logits[e] > best) {
                        best = sh_logits[e]; bi = e;
                    }
                }
                used |= (1ull << bi);
                idx[k] = bi;
                val[k] = best;
            }
            float mx = val[0];
            float denom = 0.f;
            float ex[TOP_K];
            for (int k = 0; k < TOP_K; k++) { ex[k] = expf(val[k] - mx); denom += ex[k]; }
            float rden = 1.0f / denom;
            for (int k = 0; k < TOP_K; k++)
                out[(size_t)b * NUM_EXPERTS + idx[k]] = ex[k] * rden;

            g_cnt1[b] = 0u;   // reset for next replay (all uses complete)
            g_cnt2[b] = 0u;
        }
    }
}

// ---------------------------------------------------------------------------
extern "C" void kernel_launch(void* const* d_in, const int* in_sizes, int n_in,
                              void* d_out, int out_size) {
    const float* hs   = (const float*)d_in[0];
    const float* W1   = (const float*)d_in[1];
    const float* b1   = (const float*)d_in[2];
    const float* ln_g = (const float*)d_in[3];
    const float* ln_b = (const float*)d_in[4];
    const float* W2   = (const float*)d_in[5];
    const float* b2   = (const float*)d_in[6];
    // d_in[7] = top_k (hardcoded 8)

    float* out = (float*)d_out;

    fused_router<<<BATCH * NSPLIT, NTHR>>>(hs, W1, b1, ln_g, ln_b, W2, b2, out);
}